// round 4
// baseline (speedup 1.0000x reference)
#include <cuda_runtime.h>

#define NU 100000
#define NI 50000
#define NN 150000
#define DIM 64
#define NE 1200000
#define NBATCH 4096

#define KP 68   // padded smem row stride in floats (17 float4 units -> conflict-free)

// Scratch (device globals: no allocation allowed in kernel_launch)
__device__ float         g_dinv[NN];
__device__ int           g_deg[NN];
__device__ unsigned char g_markS[NN];   // final gathered targets (users/items)
__device__ unsigned char g_markR[NN];   // rows feeding surviving prop2 edges
__device__ int           g_cnt;         // surviving edge count
__device__ int           g_list[NE];    // compacted surviving edge ids
__device__ float         g_bufA[(size_t)NN * DIM];  // prop1 output
__device__ float         g_bufB[(size_t)NN * DIM];  // prop2 output (only S rows valid)

// ---------------------------------------------------------------------------
// degree over row indices
// ---------------------------------------------------------------------------
__global__ void deg_kernel(const int* __restrict__ ei) {
    int e = blockIdx.x * blockDim.x + threadIdx.x;
    if (e < NE) atomicAdd(&g_deg[ei[e]], 1);
}

__global__ void dinv_kernel() {
    int n = blockIdx.x * blockDim.x + threadIdx.x;
    if (n < NN) {
        int d = g_deg[n];
        g_dinv[n] = (d > 0) ? rsqrtf((float)d) : 0.0f;
    }
}

// ---------------------------------------------------------------------------
// mark final targets S = users  ∪  (NU + items)
// ---------------------------------------------------------------------------
__global__ void markS_kernel(const int* __restrict__ users,
                             const int* __restrict__ items) {
    int i = blockIdx.x * blockDim.x + threadIdx.x;
    if (i < NBATCH) {
        g_markS[users[i]] = 1;
        g_markS[NU + items[i]] = 1;
    }
}

// ---------------------------------------------------------------------------
// one scan: edges with col in S -> mark row in R, append edge id to g_list
// (warp-aggregated atomic append)
// ---------------------------------------------------------------------------
__global__ void scan_compact_kernel(const int* __restrict__ ei) {
    int e = blockIdx.x * blockDim.x + threadIdx.x;
    bool pred = false;
    if (e < NE) {
        int col = ei[NE + e];
        if (g_markS[col]) {
            g_markR[ei[e]] = 1;
            pred = true;
        }
    }
    unsigned mask = __ballot_sync(0xffffffffu, pred);
    if (pred) {
        int lane = threadIdx.x & 31;
        int leader = __ffs(mask) - 1;
        int base = 0;
        if (lane == leader) base = atomicAdd(&g_cnt, __popc(mask));
        base = __shfl_sync(mask, base, leader);
        g_list[base + __popc(mask & ((1u << lane) - 1u))] = e;
    }
}

// ---------------------------------------------------------------------------
// zero bufA rows in R (prop1 targets); zero bufB rows in S (prop2 targets)
// ---------------------------------------------------------------------------
__global__ void zeroA_kernel() {
    long long t = (long long)blockIdx.x * blockDim.x + threadIdx.x;
    if (t >= (long long)NN * 16) return;
    int row = (int)(t >> 4);
    if (g_markR[row])
        reinterpret_cast<float4*>(g_bufA)[t] = make_float4(0.f, 0.f, 0.f, 0.f);
}

__global__ void zeroB_kernel(const int* __restrict__ users,
                             const int* __restrict__ items) {
    int t = blockIdx.x * blockDim.x + threadIdx.x;
    if (t >= 2 * NBATCH * 16) return;
    int elem = t >> 4, l = t & 15;
    int node = (elem < NBATCH) ? users[elem] : NU + items[elem - NBATCH];
    reinterpret_cast<float4*>(g_bufB)[(size_t)node * 16 + l] =
        make_float4(0.f, 0.f, 0.f, 0.f);
}

// ---------------------------------------------------------------------------
// prop1 (filtered): for edges with col in R: bufA[col] += w * emb[row]
// 16 lanes per edge, one red.global.add.v4.f32 each
// ---------------------------------------------------------------------------
__global__ void prop1_kernel(const int* __restrict__ ei,
                             const float* __restrict__ ue,
                             const float* __restrict__ ie) {
    long long gid = (long long)blockIdx.x * blockDim.x + threadIdx.x;
    int e = (int)(gid >> 4);
    if (e >= NE) return;
    int l = (int)gid & 15;

    int col = ei[NE + e];
    if (!g_markR[col]) return;
    int row = ei[e];
    float w = g_dinv[row] * g_dinv[col];
    if (w == 0.0f) return;

    const float* p = (row < NU) ? (ue + (size_t)row * DIM)
                                : (ie + (size_t)(row - NU) * DIM);
    float4 v = reinterpret_cast<const float4*>(p)[l];
    float* dst = g_bufA + (size_t)col * DIM + l * 4;
    asm volatile("red.global.add.v4.f32 [%0], {%1,%2,%3,%4};"
                 :: "l"(dst), "f"(v.x * w), "f"(v.y * w), "f"(v.z * w), "f"(v.w * w)
                 : "memory");
}

// ---------------------------------------------------------------------------
// fused transform + prop2 over the compacted edge list:
// bufB[col] += w * relu(bufA[row] @ W1.T + b1)
// 16 lanes per edge; lane l owns output cols [4l, 4l+4); row vector broadcast
// via width-16 shuffles; W1 staged in smem (stride KP -> conflict-free).
// ---------------------------------------------------------------------------
__global__ __launch_bounds__(256)
void prop2_kernel(const int* __restrict__ ei,
                  const float* __restrict__ W1,
                  const float* __restrict__ b1) {
    int tid = threadIdx.x;
    int cnt = g_cnt;
    if (blockIdx.x * 16 >= cnt) return;

    __shared__ float sW[DIM * KP];
    __shared__ float sb[DIM];

    for (int i = tid; i < DIM * 16; i += 256) {
        int r = i >> 4, k4 = i & 15;
        float4 v = reinterpret_cast<const float4*>(W1)[i];
        *reinterpret_cast<float4*>(&sW[r * KP + k4 * 4]) = v;
    }
    if (tid < DIM) sb[tid] = b1[tid];
    __syncthreads();

    int gi = tid >> 4;        // edge slot within block (0..15)
    int l  = tid & 15;        // lane within edge
    int idx = blockIdx.x * 16 + gi;
    bool act = idx < cnt;

    int e   = g_list[act ? idx : 0];
    int row = ei[e];
    int col = ei[NE + e];
    float w = g_dinv[row] * g_dinv[col];
    act = act && (w != 0.0f);

    float4 a = make_float4(0.f, 0.f, 0.f, 0.f);
    if (act) a = reinterpret_cast<const float4*>(g_bufA)[(size_t)row * 16 + l];

    int c0 = l * 4;
    float acc0 = sb[c0], acc1 = sb[c0 + 1], acc2 = sb[c0 + 2], acc3 = sb[c0 + 3];

#pragma unroll
    for (int k4 = 0; k4 < 16; k4++) {
        float x0 = __shfl_sync(0xffffffffu, a.x, k4, 16);
        float x1 = __shfl_sync(0xffffffffu, a.y, k4, 16);
        float x2 = __shfl_sync(0xffffffffu, a.z, k4, 16);
        float x3 = __shfl_sync(0xffffffffu, a.w, k4, 16);
        float4 w0 = *reinterpret_cast<const float4*>(&sW[(c0 + 0) * KP + k4 * 4]);
        float4 w1 = *reinterpret_cast<const float4*>(&sW[(c0 + 1) * KP + k4 * 4]);
        float4 w2 = *reinterpret_cast<const float4*>(&sW[(c0 + 2) * KP + k4 * 4]);
        float4 w3 = *reinterpret_cast<const float4*>(&sW[(c0 + 3) * KP + k4 * 4]);
        acc0 += x0 * w0.x + x1 * w0.y + x2 * w0.z + x3 * w0.w;
        acc1 += x0 * w1.x + x1 * w1.y + x2 * w1.z + x3 * w1.w;
        acc2 += x0 * w2.x + x1 * w2.y + x2 * w2.z + x3 * w2.w;
        acc3 += x0 * w3.x + x1 * w3.y + x2 * w3.z + x3 * w3.w;
    }

    if (act) {
        float m0 = fmaxf(acc0, 0.f) * w;
        float m1 = fmaxf(acc1, 0.f) * w;
        float m2 = fmaxf(acc2, 0.f) * w;
        float m3 = fmaxf(acc3, 0.f) * w;
        float* dst = g_bufB + (size_t)col * DIM + c0;
        asm volatile("red.global.add.v4.f32 [%0], {%1,%2,%3,%4};"
                     :: "l"(dst), "f"(m0), "f"(m1), "f"(m2), "f"(m3)
                     : "memory");
    }
}

// ---------------------------------------------------------------------------
// score: W2/b2 staged once per block (8 blocks); each warp handles 64 batch
// elements. Per element: u' = h[u]@W2.T+b2, v' = h[NU+it]@W2.T+b2, out = u'.v'
// ---------------------------------------------------------------------------
__global__ __launch_bounds__(256)
void score_kernel(const int* __restrict__ users,
                  const int* __restrict__ items,
                  const float* __restrict__ W2,
                  const float* __restrict__ b2,
                  float* __restrict__ out) {
    __shared__ float sW[DIM * KP];
    __shared__ float sb[DIM];
    __shared__ float sU[8][DIM];
    __shared__ float sV[8][DIM];

    int tid = threadIdx.x;
    for (int i = tid; i < DIM * 16; i += 256) {
        int r = i >> 4, k4 = i & 15;
        float4 v = reinterpret_cast<const float4*>(W2)[i];
        *reinterpret_cast<float4*>(&sW[r * KP + k4 * 4]) = v;
    }
    if (tid < DIM) sb[tid] = b2[tid];
    __syncthreads();

    int wid = tid >> 5, lane = tid & 31;
    int base = (blockIdx.x * 8 + wid) * 64;

    for (int t = 0; t < 64; t++) {
        int bi = base + t;
        int u  = users[bi];
        int it = items[bi];
        sU[wid][lane]      = g_bufB[(size_t)u * DIM + lane];
        sU[wid][lane + 32] = g_bufB[(size_t)u * DIM + 32 + lane];
        sV[wid][lane]      = g_bufB[(size_t)(NU + it) * DIM + lane];
        sV[wid][lane + 32] = g_bufB[(size_t)(NU + it) * DIM + 32 + lane];
        __syncwarp();

        float uo0 = sb[lane], vo0 = sb[lane];
        float uo1 = sb[lane + 32], vo1 = sb[lane + 32];
#pragma unroll
        for (int k4 = 0; k4 < 16; k4++) {
            float4 su4 = *reinterpret_cast<const float4*>(&sU[wid][k4 * 4]);
            float4 sv4 = *reinterpret_cast<const float4*>(&sV[wid][k4 * 4]);
            float4 wa  = *reinterpret_cast<const float4*>(&sW[lane * KP + k4 * 4]);
            float4 wb  = *reinterpret_cast<const float4*>(&sW[(lane + 32) * KP + k4 * 4]);
            uo0 += su4.x * wa.x + su4.y * wa.y + su4.z * wa.z + su4.w * wa.w;
            vo0 += sv4.x * wa.x + sv4.y * wa.y + sv4.z * wa.z + sv4.w * wa.w;
            uo1 += su4.x * wb.x + su4.y * wb.y + su4.z * wb.z + su4.w * wb.w;
            vo1 += sv4.x * wb.x + sv4.y * wb.y + sv4.z * wb.z + sv4.w * wb.w;
        }
        float s = uo0 * vo0 + uo1 * vo1;
#pragma unroll
        for (int o = 16; o > 0; o >>= 1)
            s += __shfl_down_sync(0xffffffffu, s, o);
        if (lane == 0) out[bi] = s;
        __syncwarp();
    }
}

// ---------------------------------------------------------------------------
extern "C" void kernel_launch(void* const* d_in, const int* in_sizes, int n_in,
                              void* d_out, int out_size) {
    const int*   users = (const int*)d_in[0];
    const int*   items = (const int*)d_in[1];
    const int*   ei    = (const int*)d_in[2];
    const float* ue    = (const float*)d_in[3];
    const float* ie    = (const float*)d_in[4];
    const float* W1    = (const float*)d_in[5];
    const float* b1    = (const float*)d_in[6];
    const float* W2    = (const float*)d_in[7];
    const float* b2    = (const float*)d_in[8];
    float* out = (float*)d_out;

    void *pDeg, *pMS, *pMR, *pCnt;
    cudaGetSymbolAddress(&pDeg, g_deg);
    cudaGetSymbolAddress(&pMS, g_markS);
    cudaGetSymbolAddress(&pMR, g_markR);
    cudaGetSymbolAddress(&pCnt, g_cnt);

    cudaMemsetAsync(pDeg, 0, NN * sizeof(int), 0);
    cudaMemsetAsync(pMS, 0, NN, 0);
    cudaMemsetAsync(pMR, 0, NN, 0);
    cudaMemsetAsync(pCnt, 0, sizeof(int), 0);

    markS_kernel<<<(NBATCH + 255) / 256, 256>>>(users, items);
    deg_kernel<<<(NE + 255) / 256, 256>>>(ei);
    scan_compact_kernel<<<(NE + 255) / 256, 256>>>(ei);
    dinv_kernel<<<(NN + 255) / 256, 256>>>();

    zeroA_kernel<<<(NN * 16 + 255) / 256, 256>>>();
    zeroB_kernel<<<(2 * NBATCH * 16 + 255) / 256, 256>>>(users, items);

    // prop1 (filtered to cols in R): source = concat(user_emb, item_emb)
    prop1_kernel<<<(NE * 16 + 255) / 256, 256>>>(ei, ue, ie);

    // fused relu(A@W1.T+b1) + prop2 over compacted surviving edges
    prop2_kernel<<<(NE + 15) / 16, 256>>>(ei, W1, b1);

    // score with W2 staged once per block
    score_kernel<<<NBATCH / (8 * 64), 256>>>(users, items, W2, b2, out);
}

// round 5
// speedup vs baseline: 1.7203x; 1.7203x over previous
#include <cuda_runtime.h>

#define NU 100000
#define NI 50000
#define NN 150000
#define DIM 64
#define NE 1200000
#define NBATCH 4096

#define KP 68   // padded smem row stride in floats (17 float4 units -> conflict-free)

// Scratch (device globals: no allocation allowed in kernel_launch)
__device__ float         g_dinv[NN];
__device__ int           g_deg[NN];
__device__ unsigned char g_markS[NN];   // final gathered targets (users/items)
__device__ unsigned char g_markR[NN];   // rows feeding surviving prop2 edges
__device__ int           g_cnt[2];      // [0]=prop1 list count, [1]=prop2 list count
__device__ int           g_list1[NE];   // edges with col in R  (~504K)
__device__ int           g_list2[NE];   // edges with col in S  (~65K)
__device__ float         g_bufA[(size_t)NN * DIM];  // prop1 output
__device__ float         g_bufB[(size_t)NN * DIM];  // prop2 output (S rows valid)

// ---------------------------------------------------------------------------
__global__ void deg_kernel(const int* __restrict__ ei) {
    int e = blockIdx.x * blockDim.x + threadIdx.x;
    if (e < NE) atomicAdd(&g_deg[ei[e]], 1);
}

__global__ void dinv_kernel() {
    int n = blockIdx.x * blockDim.x + threadIdx.x;
    if (n < NN) {
        int d = g_deg[n];
        g_dinv[n] = (d > 0) ? rsqrtf((float)d) : 0.0f;
    }
}

__global__ void markS_kernel(const int* __restrict__ users,
                             const int* __restrict__ items) {
    int i = blockIdx.x * blockDim.x + threadIdx.x;
    if (i < NBATCH) {
        g_markS[users[i]] = 1;
        g_markS[NU + items[i]] = 1;
    }
}

// ---------------------------------------------------------------------------
// scan1: edges with col in S -> mark row in R, compact into list2.
// Block-aggregated append (one global atomic per block).
// ---------------------------------------------------------------------------
__global__ __launch_bounds__(256)
void scan1_kernel(const int* __restrict__ ei) {
    __shared__ int wBase[8];
    __shared__ int bBase;
    int tid = threadIdx.x;
    int e = blockIdx.x * 256 + tid;
    bool pred = false;
    if (e < NE) {
        int col = ei[NE + e];
        if (g_markS[col]) { g_markR[ei[e]] = 1; pred = true; }
    }
    unsigned mask = __ballot_sync(0xffffffffu, pred);
    int lane = tid & 31, wid = tid >> 5;
    if (lane == 0) wBase[wid] = __popc(mask);
    __syncthreads();
    if (tid == 0) {
        int tot = 0;
#pragma unroll
        for (int w = 0; w < 8; w++) { int c = wBase[w]; wBase[w] = tot; tot += c; }
        bBase = tot ? atomicAdd(&g_cnt[1], tot) : 0;
    }
    __syncthreads();
    if (pred)
        g_list2[bBase + wBase[wid] + __popc(mask & ((1u << lane) - 1u))] = e;
}

// ---------------------------------------------------------------------------
// scan2: edges with col in R -> compact into list1 (runs after scan1)
// ---------------------------------------------------------------------------
__global__ __launch_bounds__(256)
void scan2_kernel(const int* __restrict__ ei) {
    __shared__ int wBase[8];
    __shared__ int bBase;
    int tid = threadIdx.x;
    int e = blockIdx.x * 256 + tid;
    bool pred = (e < NE) && g_markR[ei[NE + e]];
    unsigned mask = __ballot_sync(0xffffffffu, pred);
    int lane = tid & 31, wid = tid >> 5;
    if (lane == 0) wBase[wid] = __popc(mask);
    __syncthreads();
    if (tid == 0) {
        int tot = 0;
#pragma unroll
        for (int w = 0; w < 8; w++) { int c = wBase[w]; wBase[w] = tot; tot += c; }
        bBase = tot ? atomicAdd(&g_cnt[0], tot) : 0;
    }
    __syncthreads();
    if (pred)
        g_list1[bBase + wBase[wid] + __popc(mask & ((1u << lane) - 1u))] = e;
}

// ---------------------------------------------------------------------------
// zero bufA rows in R; zero bufB rows in S
// ---------------------------------------------------------------------------
__global__ void zeroA_kernel() {
    long long t = (long long)blockIdx.x * blockDim.x + threadIdx.x;
    if (t >= (long long)NN * 16) return;
    int row = (int)(t >> 4);
    if (g_markR[row])
        reinterpret_cast<float4*>(g_bufA)[t] = make_float4(0.f, 0.f, 0.f, 0.f);
}

__global__ void zeroB_kernel(const int* __restrict__ users,
                             const int* __restrict__ items) {
    int t = blockIdx.x * blockDim.x + threadIdx.x;
    if (t >= 2 * NBATCH * 16) return;
    int elem = t >> 4, l = t & 15;
    int node = (elem < NBATCH) ? users[elem] : NU + items[elem - NBATCH];
    reinterpret_cast<float4*>(g_bufB)[(size_t)node * 16 + l] =
        make_float4(0.f, 0.f, 0.f, 0.f);
}

// ---------------------------------------------------------------------------
// prop1 over compacted list1: bufA[col] += w * emb[row]
// 4 threads/edge, each does 4 independent LDG.128 then 4 RED.128 (MLP=4).
// Grid-stride (count is data-dependent).
// ---------------------------------------------------------------------------
__global__ __launch_bounds__(256)
void prop1_kernel(const int* __restrict__ ei,
                  const float* __restrict__ ue,
                  const float* __restrict__ ie) {
    int cnt = g_cnt[0];
    int tid = blockIdx.x * 256 + threadIdx.x;
    int l = tid & 3;
    int i0 = tid >> 2;
    int stride = (gridDim.x * 256) >> 2;

    for (int i = i0; i < cnt; i += stride) {
        int e = g_list1[i];
        int row = ei[e];
        int col = ei[NE + e];
        float w = g_dinv[row] * g_dinv[col];
        if (w == 0.0f) continue;

        const float4* p = reinterpret_cast<const float4*>(
            (row < NU) ? (ue + (size_t)row * DIM)
                       : (ie + (size_t)(row - NU) * DIM));
        float4 v0 = p[0 * 4 + l];
        float4 v1 = p[1 * 4 + l];
        float4 v2 = p[2 * 4 + l];
        float4 v3 = p[3 * 4 + l];
        float* dst = g_bufA + (size_t)col * DIM;
#define RED4(V, OFF) \
        asm volatile("red.global.add.v4.f32 [%0], {%1,%2,%3,%4};" \
                     :: "l"(dst + (OFF)), "f"((V).x * w), "f"((V).y * w), \
                        "f"((V).z * w), "f"((V).w * w) : "memory")
        RED4(v0, (0 * 4 + l) * 4);
        RED4(v1, (1 * 4 + l) * 4);
        RED4(v2, (2 * 4 + l) * 4);
        RED4(v3, (3 * 4 + l) * 4);
#undef RED4
    }
}

// ---------------------------------------------------------------------------
// prop2 over compacted list2: bufB[col] += w * relu(bufA[row] @ W1.T + b1)
// 16 threads/edge, 16 edges per block-iteration, grid-stride.
// Row vector broadcast via width-16 shuffles; W1 staged in smem.
// ---------------------------------------------------------------------------
__global__ __launch_bounds__(256)
void prop2_kernel(const int* __restrict__ ei,
                  const float* __restrict__ W1,
                  const float* __restrict__ b1) {
    __shared__ float sW[DIM * KP];
    __shared__ float sb[DIM];

    int tid = threadIdx.x;
    int cnt = g_cnt[1];

    for (int i = tid; i < DIM * 16; i += 256) {
        int r = i >> 4, k4 = i & 15;
        float4 v = reinterpret_cast<const float4*>(W1)[i];
        *reinterpret_cast<float4*>(&sW[r * KP + k4 * 4]) = v;
    }
    if (tid < DIM) sb[tid] = b1[tid];
    __syncthreads();

    int gi = tid >> 4;        // edge slot within block (0..15)
    int l  = tid & 15;        // lane within edge
    int c0 = l * 4;

    for (int base = blockIdx.x * 16; base < cnt; base += gridDim.x * 16) {
        int idx = base + gi;
        bool act = idx < cnt;

        int e   = g_list2[act ? idx : 0];
        int row = ei[e];
        int col = ei[NE + e];
        float w = g_dinv[row] * g_dinv[col];
        act = act && (w != 0.0f);

        float4 a = make_float4(0.f, 0.f, 0.f, 0.f);
        if (act) a = reinterpret_cast<const float4*>(g_bufA)[(size_t)row * 16 + l];

        float acc0 = sb[c0], acc1 = sb[c0 + 1], acc2 = sb[c0 + 2], acc3 = sb[c0 + 3];

#pragma unroll
        for (int k4 = 0; k4 < 16; k4++) {
            float x0 = __shfl_sync(0xffffffffu, a.x, k4, 16);
            float x1 = __shfl_sync(0xffffffffu, a.y, k4, 16);
            float x2 = __shfl_sync(0xffffffffu, a.z, k4, 16);
            float x3 = __shfl_sync(0xffffffffu, a.w, k4, 16);
            float4 w0 = *reinterpret_cast<const float4*>(&sW[(c0 + 0) * KP + k4 * 4]);
            float4 w1 = *reinterpret_cast<const float4*>(&sW[(c0 + 1) * KP + k4 * 4]);
            float4 w2 = *reinterpret_cast<const float4*>(&sW[(c0 + 2) * KP + k4 * 4]);
            float4 w3 = *reinterpret_cast<const float4*>(&sW[(c0 + 3) * KP + k4 * 4]);
            acc0 += x0 * w0.x + x1 * w0.y + x2 * w0.z + x3 * w0.w;
            acc1 += x0 * w1.x + x1 * w1.y + x2 * w1.z + x3 * w1.w;
            acc2 += x0 * w2.x + x1 * w2.y + x2 * w2.z + x3 * w2.w;
            acc3 += x0 * w3.x + x1 * w3.y + x2 * w3.z + x3 * w3.w;
        }

        if (act) {
            float m0 = fmaxf(acc0, 0.f) * w;
            float m1 = fmaxf(acc1, 0.f) * w;
            float m2 = fmaxf(acc2, 0.f) * w;
            float m3 = fmaxf(acc3, 0.f) * w;
            float* dst = g_bufB + (size_t)col * DIM + c0;
            asm volatile("red.global.add.v4.f32 [%0], {%1,%2,%3,%4};"
                         :: "l"(dst), "f"(m0), "f"(m1), "f"(m2), "f"(m3)
                         : "memory");
        }
    }
}

// ---------------------------------------------------------------------------
// score: 512 blocks x 8 warps; ONE warp per batch element (fully parallel).
// W2/b2 staged per block. u' = h[u]@W2.T+b2, v' = h[NU+it]@W2.T+b2, out=u'.v'
// ---------------------------------------------------------------------------
__global__ __launch_bounds__(256)
void score_kernel(const int* __restrict__ users,
                  const int* __restrict__ items,
                  const float* __restrict__ W2,
                  const float* __restrict__ b2,
                  float* __restrict__ out) {
    __shared__ float sW[DIM * KP];
    __shared__ float sb[DIM];
    __shared__ float4 sUV[8][2][16];   // per-warp staged u and v rows

    int tid = threadIdx.x;
    for (int i = tid; i < DIM * 16; i += 256) {
        int r = i >> 4, k4 = i & 15;
        float4 v = reinterpret_cast<const float4*>(W2)[i];
        *reinterpret_cast<float4*>(&sW[r * KP + k4 * 4]) = v;
    }
    if (tid < DIM) sb[tid] = b2[tid];
    __syncthreads();

    int wid = tid >> 5, lane = tid & 31;
    int bi = blockIdx.x * 8 + wid;      // exactly 4096

    int u  = users[bi];
    int it = items[bi];
    // lanes 0-15 stage u row, lanes 16-31 stage v row (16 float4 each)
    if (lane < 16)
        sUV[wid][0][lane] = reinterpret_cast<const float4*>(g_bufB)[(size_t)u * 16 + lane];
    else
        sUV[wid][1][lane - 16] =
            reinterpret_cast<const float4*>(g_bufB)[(size_t)(NU + it) * 16 + (lane - 16)];
    __syncwarp();

    float uo = sb[lane], vo = sb[lane];
    float uo1 = sb[lane + 32], vo1 = sb[lane + 32];
#pragma unroll
    for (int k4 = 0; k4 < 16; k4++) {
        float4 su4 = sUV[wid][0][k4];
        float4 sv4 = sUV[wid][1][k4];
        float4 wa  = *reinterpret_cast<const float4*>(&sW[lane * KP + k4 * 4]);
        float4 wb  = *reinterpret_cast<const float4*>(&sW[(lane + 32) * KP + k4 * 4]);
        uo  += su4.x * wa.x + su4.y * wa.y + su4.z * wa.z + su4.w * wa.w;
        vo  += sv4.x * wa.x + sv4.y * wa.y + sv4.z * wa.z + sv4.w * wa.w;
        uo1 += su4.x * wb.x + su4.y * wb.y + su4.z * wb.z + su4.w * wb.w;
        vo1 += sv4.x * wb.x + sv4.y * wb.y + sv4.z * wb.z + sv4.w * wb.w;
    }
    float s = uo * vo + uo1 * vo1;
#pragma unroll
    for (int o = 16; o > 0; o >>= 1)
        s += __shfl_down_sync(0xffffffffu, s, o);
    if (lane == 0) out[bi] = s;
}

// ---------------------------------------------------------------------------
extern "C" void kernel_launch(void* const* d_in, const int* in_sizes, int n_in,
                              void* d_out, int out_size) {
    const int*   users = (const int*)d_in[0];
    const int*   items = (const int*)d_in[1];
    const int*   ei    = (const int*)d_in[2];
    const float* ue    = (const float*)d_in[3];
    const float* ie    = (const float*)d_in[4];
    const float* W1    = (const float*)d_in[5];
    const float* b1    = (const float*)d_in[6];
    const float* W2    = (const float*)d_in[7];
    const float* b2    = (const float*)d_in[8];
    float* out = (float*)d_out;

    void *pDeg, *pMS, *pMR, *pCnt;
    cudaGetSymbolAddress(&pDeg, g_deg);
    cudaGetSymbolAddress(&pMS, g_markS);
    cudaGetSymbolAddress(&pMR, g_markR);
    cudaGetSymbolAddress(&pCnt, g_cnt);

    cudaMemsetAsync(pDeg, 0, NN * sizeof(int), 0);
    cudaMemsetAsync(pMS, 0, NN, 0);
    cudaMemsetAsync(pMR, 0, NN, 0);
    cudaMemsetAsync(pCnt, 0, 2 * sizeof(int), 0);

    markS_kernel<<<(NBATCH + 255) / 256, 256>>>(users, items);
    deg_kernel<<<(NE + 255) / 256, 256>>>(ei);
    scan1_kernel<<<(NE + 255) / 256, 256>>>(ei);   // needs markS
    dinv_kernel<<<(NN + 255) / 256, 256>>>();
    scan2_kernel<<<(NE + 255) / 256, 256>>>(ei);   // needs markR (from scan1)

    zeroA_kernel<<<(NN * 16 + 255) / 256, 256>>>();
    zeroB_kernel<<<(2 * NBATCH * 16 + 255) / 256, 256>>>(users, items);

    prop1_kernel<<<2048, 256>>>(ei, ue, ie);       // grid-stride over list1
    prop2_kernel<<<1024, 256>>>(ei, W1, b1);       // grid-stride over list2
    score_kernel<<<NBATCH / 8, 256>>>(users, items, W2, b2, out);
}

// round 6
// speedup vs baseline: 1.7614x; 1.0239x over previous
#include <cuda_runtime.h>

#define NU 100000
#define NI 50000
#define NN 150000
#define DIM 64
#define NE 1200000
#define NBATCH 4096

#define KP 68   // padded smem row stride in floats (17 float4 units -> conflict-free)

// ---------------------------------------------------------------------------
// All zero-initialized scratch in ONE contiguous struct -> ONE memset node.
// ---------------------------------------------------------------------------
struct ZeroBlock {
    int           deg[NN];
    int           cnt1;       // list1 count (prop1 edges, col in R)
    int           cnt2;       // list2 count (prop2 edges, col in S)
    unsigned char markS[NN];  // final gathered targets (users/items)
    unsigned char markR[NN];  // rows feeding surviving prop2 edges
};
__device__ ZeroBlock gz;

__device__ int2  g_rc1[NE];   // (row, col) for prop1 edges
__device__ float g_w1[NE];    // precomputed weight for prop1 edges
__device__ int2  g_rc2[NE];   // (row, col) for prop2 edges
__device__ float g_bufA[(size_t)NN * DIM];  // prop1 output
__device__ float g_bufB[(size_t)NN * DIM];  // prop2 output (S rows valid)

// ---------------------------------------------------------------------------
// markS + zeroB fused: mark final targets and zero their bufB rows
// ---------------------------------------------------------------------------
__global__ void markS_zeroB_kernel(const int* __restrict__ users,
                                   const int* __restrict__ items) {
    int t = blockIdx.x * blockDim.x + threadIdx.x;
    if (t >= 2 * NBATCH * 16) return;
    int elem = t >> 4, l = t & 15;
    int node = (elem < NBATCH) ? users[elem] : NU + items[elem - NBATCH];
    if (l == 0) gz.markS[node] = 1;
    reinterpret_cast<float4*>(g_bufB)[(size_t)node * 16 + l] =
        make_float4(0.f, 0.f, 0.f, 0.f);
}

// ---------------------------------------------------------------------------
// deg + scan1 fused (one edge pass): deg[row]++, and edges with col in S
// -> mark row in R, append (row,col) to list2. Block-aggregated append.
// ---------------------------------------------------------------------------
__global__ __launch_bounds__(256)
void deg_scan1_kernel(const int* __restrict__ ei) {
    __shared__ int wBase[8];
    __shared__ int bBase;
    int tid = threadIdx.x;
    int e = blockIdx.x * 256 + tid;
    int row = 0, col = 0;
    bool pred = false;
    if (e < NE) {
        row = ei[e];
        col = ei[NE + e];
        atomicAdd(&gz.deg[row], 1);
        if (gz.markS[col]) { gz.markR[row] = 1; pred = true; }
    }
    unsigned mask = __ballot_sync(0xffffffffu, pred);
    int lane = tid & 31, wid = tid >> 5;
    if (lane == 0) wBase[wid] = __popc(mask);
    __syncthreads();
    if (tid == 0) {
        int tot = 0;
#pragma unroll
        for (int w = 0; w < 8; w++) { int c = wBase[w]; wBase[w] = tot; tot += c; }
        bBase = tot ? atomicAdd(&gz.cnt2, tot) : 0;
    }
    __syncthreads();
    if (pred)
        g_rc2[bBase + wBase[wid] + __popc(mask & ((1u << lane) - 1u))] =
            make_int2(row, col);
}

// ---------------------------------------------------------------------------
// scan2 + zeroA fused (both depend only on scan1 output):
// phase A: edges with col in R -> append (row,col)+w to list1 (deg is final,
//          and both endpoints have deg>=1, so w>0 always -- no check needed)
// phase B: zero bufA rows in R (grid-stride)
// ---------------------------------------------------------------------------
__global__ __launch_bounds__(256)
void scan2_zeroA_kernel(const int* __restrict__ ei) {
    __shared__ int wBase[8];
    __shared__ int bBase;
    int tid = threadIdx.x;
    int e = blockIdx.x * 256 + tid;
    int row = 0, col = 0;
    bool pred = false;
    if (e < NE) {
        row = ei[e];
        col = ei[NE + e];
        pred = gz.markR[col] != 0;
    }
    unsigned mask = __ballot_sync(0xffffffffu, pred);
    int lane = tid & 31, wid = tid >> 5;
    if (lane == 0) wBase[wid] = __popc(mask);
    __syncthreads();
    if (tid == 0) {
        int tot = 0;
#pragma unroll
        for (int w = 0; w < 8; w++) { int c = wBase[w]; wBase[w] = tot; tot += c; }
        bBase = tot ? atomicAdd(&gz.cnt1, tot) : 0;
    }
    __syncthreads();
    if (pred) {
        int pos = bBase + wBase[wid] + __popc(mask & ((1u << lane) - 1u));
        g_rc1[pos] = make_int2(row, col);
        g_w1[pos]  = rsqrtf((float)gz.deg[row]) * rsqrtf((float)gz.deg[col]);
    }

    // phase B: conditional zero of bufA rows (markR written by scan1, read-only here)
    long long total = (long long)NN * 16;
    for (long long t = (long long)blockIdx.x * 256 + tid; t < total;
         t += (long long)gridDim.x * 256) {
        int r = (int)(t >> 4);
        if (gz.markR[r])
            reinterpret_cast<float4*>(g_bufA)[t] = make_float4(0.f, 0.f, 0.f, 0.f);
    }
}

// ---------------------------------------------------------------------------
// prop1 over list1: bufA[col] += w * emb[row]
// Coalesced (row,col,w) stream; 4 threads/edge, 4 LDG.128 + 4 RED.128 (MLP=4)
// ---------------------------------------------------------------------------
__global__ __launch_bounds__(256)
void prop1_kernel(const float* __restrict__ ue,
                  const float* __restrict__ ie) {
    int cnt = gz.cnt1;
    int t = blockIdx.x * 256 + threadIdx.x;
    int l = t & 3;
    int i0 = t >> 2;
    int stride = (gridDim.x * 256) >> 2;

    for (int i = i0; i < cnt; i += stride) {
        int2  rc = g_rc1[i];
        float w  = g_w1[i];
        const float4* p = reinterpret_cast<const float4*>(
            (rc.x < NU) ? (ue + (size_t)rc.x * DIM)
                        : (ie + (size_t)(rc.x - NU) * DIM));
        float4 v0 = p[0 * 4 + l];
        float4 v1 = p[1 * 4 + l];
        float4 v2 = p[2 * 4 + l];
        float4 v3 = p[3 * 4 + l];
        float* dst = g_bufA + (size_t)rc.y * DIM;
#define RED4(V, OFF) \
        asm volatile("red.global.add.v4.f32 [%0], {%1,%2,%3,%4};" \
                     :: "l"(dst + (OFF)), "f"((V).x * w), "f"((V).y * w), \
                        "f"((V).z * w), "f"((V).w * w) : "memory")
        RED4(v0, (0 * 4 + l) * 4);
        RED4(v1, (1 * 4 + l) * 4);
        RED4(v2, (2 * 4 + l) * 4);
        RED4(v3, (3 * 4 + l) * 4);
#undef RED4
    }
}

// ---------------------------------------------------------------------------
// prop2 over list2: bufB[col] += w * relu(bufA[row] @ W1.T + b1)
// 16 threads/edge; row vector broadcast via width-16 shuffles; W1 in smem.
// w computed inline from deg (col in S may have deg 0 -> skip).
// ---------------------------------------------------------------------------
__global__ __launch_bounds__(256)
void prop2_kernel(const float* __restrict__ W1,
                  const float* __restrict__ b1) {
    __shared__ float sW[DIM * KP];
    __shared__ float sb[DIM];

    int tid = threadIdx.x;
    int cnt = gz.cnt2;

    for (int i = tid; i < DIM * 16; i += 256) {
        int r = i >> 4, k4 = i & 15;
        float4 v = reinterpret_cast<const float4*>(W1)[i];
        *reinterpret_cast<float4*>(&sW[r * KP + k4 * 4]) = v;
    }
    if (tid < DIM) sb[tid] = b1[tid];
    __syncthreads();

    int gi = tid >> 4;
    int l  = tid & 15;
    int c0 = l * 4;

    for (int base = blockIdx.x * 16; base < cnt; base += gridDim.x * 16) {
        int idx = base + gi;
        bool act = idx < cnt;

        int2 rc = g_rc2[act ? idx : 0];
        int dc = gz.deg[rc.y];
        float w = (dc > 0) ? rsqrtf((float)gz.deg[rc.x]) * rsqrtf((float)dc) : 0.0f;
        act = act && (w != 0.0f);

        float4 a = make_float4(0.f, 0.f, 0.f, 0.f);
        if (act) a = reinterpret_cast<const float4*>(g_bufA)[(size_t)rc.x * 16 + l];

        float acc0 = sb[c0], acc1 = sb[c0 + 1], acc2 = sb[c0 + 2], acc3 = sb[c0 + 3];

#pragma unroll
        for (int k4 = 0; k4 < 16; k4++) {
            float x0 = __shfl_sync(0xffffffffu, a.x, k4, 16);
            float x1 = __shfl_sync(0xffffffffu, a.y, k4, 16);
            float x2 = __shfl_sync(0xffffffffu, a.z, k4, 16);
            float x3 = __shfl_sync(0xffffffffu, a.w, k4, 16);
            float4 w0 = *reinterpret_cast<const float4*>(&sW[(c0 + 0) * KP + k4 * 4]);
            float4 w1 = *reinterpret_cast<const float4*>(&sW[(c0 + 1) * KP + k4 * 4]);
            float4 w2 = *reinterpret_cast<const float4*>(&sW[(c0 + 2) * KP + k4 * 4]);
            float4 w3 = *reinterpret_cast<const float4*>(&sW[(c0 + 3) * KP + k4 * 4]);
            acc0 += x0 * w0.x + x1 * w0.y + x2 * w0.z + x3 * w0.w;
            acc1 += x0 * w1.x + x1 * w1.y + x2 * w1.z + x3 * w1.w;
            acc2 += x0 * w2.x + x1 * w2.y + x2 * w2.z + x3 * w2.w;
            acc3 += x0 * w3.x + x1 * w3.y + x2 * w3.z + x3 * w3.w;
        }

        if (act) {
            float m0 = fmaxf(acc0, 0.f) * w;
            float m1 = fmaxf(acc1, 0.f) * w;
            float m2 = fmaxf(acc2, 0.f) * w;
            float m3 = fmaxf(acc3, 0.f) * w;
            float* dst = g_bufB + (size_t)rc.y * DIM + c0;
            asm volatile("red.global.add.v4.f32 [%0], {%1,%2,%3,%4};"
                         :: "l"(dst), "f"(m0), "f"(m1), "f"(m2), "f"(m3)
                         : "memory");
        }
    }
}

// ---------------------------------------------------------------------------
// score: 512 blocks x 8 warps; ONE warp per batch element.
// ---------------------------------------------------------------------------
__global__ __launch_bounds__(256)
void score_kernel(const int* __restrict__ users,
                  const int* __restrict__ items,
                  const float* __restrict__ W2,
                  const float* __restrict__ b2,
                  float* __restrict__ out) {
    __shared__ float sW[DIM * KP];
    __shared__ float sb[DIM];
    __shared__ float4 sUV[8][2][16];

    int tid = threadIdx.x;
    for (int i = tid; i < DIM * 16; i += 256) {
        int r = i >> 4, k4 = i & 15;
        float4 v = reinterpret_cast<const float4*>(W2)[i];
        *reinterpret_cast<float4*>(&sW[r * KP + k4 * 4]) = v;
    }
    if (tid < DIM) sb[tid] = b2[tid];
    __syncthreads();

    int wid = tid >> 5, lane = tid & 31;
    int bi = blockIdx.x * 8 + wid;

    int u  = users[bi];
    int it = items[bi];
    if (lane < 16)
        sUV[wid][0][lane] = reinterpret_cast<const float4*>(g_bufB)[(size_t)u * 16 + lane];
    else
        sUV[wid][1][lane - 16] =
            reinterpret_cast<const float4*>(g_bufB)[(size_t)(NU + it) * 16 + (lane - 16)];
    __syncwarp();

    float uo = sb[lane], vo = sb[lane];
    float uo1 = sb[lane + 32], vo1 = sb[lane + 32];
#pragma unroll
    for (int k4 = 0; k4 < 16; k4++) {
        float4 su4 = sUV[wid][0][k4];
        float4 sv4 = sUV[wid][1][k4];
        float4 wa  = *reinterpret_cast<const float4*>(&sW[lane * KP + k4 * 4]);
        float4 wb  = *reinterpret_cast<const float4*>(&sW[(lane + 32) * KP + k4 * 4]);
        uo  += su4.x * wa.x + su4.y * wa.y + su4.z * wa.z + su4.w * wa.w;
        vo  += sv4.x * wa.x + sv4.y * wa.y + sv4.z * wa.z + sv4.w * wa.w;
        uo1 += su4.x * wb.x + su4.y * wb.y + su4.z * wb.z + su4.w * wb.w;
        vo1 += sv4.x * wb.x + sv4.y * wb.y + sv4.z * wb.z + sv4.w * wb.w;
    }
    float s = uo * vo + uo1 * vo1;
#pragma unroll
    for (int o = 16; o > 0; o >>= 1)
        s += __shfl_down_sync(0xffffffffu, s, o);
    if (lane == 0) out[bi] = s;
}

// ---------------------------------------------------------------------------
extern "C" void kernel_launch(void* const* d_in, const int* in_sizes, int n_in,
                              void* d_out, int out_size) {
    const int*   users = (const int*)d_in[0];
    const int*   items = (const int*)d_in[1];
    const int*   ei    = (const int*)d_in[2];
    const float* ue    = (const float*)d_in[3];
    const float* ie    = (const float*)d_in[4];
    const float* W1    = (const float*)d_in[5];
    const float* b1    = (const float*)d_in[6];
    const float* W2    = (const float*)d_in[7];
    const float* b2    = (const float*)d_in[8];
    float* out = (float*)d_out;

    void* pZ;
    cudaGetSymbolAddress(&pZ, gz);
    cudaMemsetAsync(pZ, 0, sizeof(ZeroBlock), 0);

    markS_zeroB_kernel<<<(2 * NBATCH * 16 + 255) / 256, 256>>>(users, items);
    deg_scan1_kernel<<<(NE + 255) / 256, 256>>>(ei);
    scan2_zeroA_kernel<<<(NE + 255) / 256, 256>>>(ei);
    prop1_kernel<<<2048, 256>>>(ue, ie);
    prop2_kernel<<<1024, 256>>>(W1, b1);
    score_kernel<<<NBATCH / 8, 256>>>(users, items, W2, b2, out);
}

// round 16
// speedup vs baseline: 1.9081x; 1.0833x over previous
#include <cuda_runtime.h>

#define NU 100000
#define NI 50000
#define NN 150000
#define DIM 64
#define NE 1200000
#define NBATCH 4096

#define KP 68   // padded smem row stride in floats (17 float4 units -> conflict-free)

// ---------------------------------------------------------------------------
// All zero-initialized scratch in ONE contiguous struct -> ONE memset node.
// ---------------------------------------------------------------------------
struct ZeroBlock {
    int           deg[NN];
    int           cnt1;       // list1 count (prop1 edges, col in R)
    int           cnt2;       // list2 count (prop2 edges, col in S)
    unsigned char markS[NN];  // final gathered targets (users/items)
    unsigned char markR[NN];  // rows feeding surviving prop2 edges
};
__device__ ZeroBlock gz;

__device__ int2  g_rc1[NE];   // (row, col) for prop1 edges
__device__ float g_w1[NE];    // precomputed weight for prop1 edges
__device__ int2  g_rc2[NE];   // (row, col) for prop2 edges
__device__ float g_bufA[(size_t)NN * DIM];  // prop1 output
__device__ float g_bufB[(size_t)NN * DIM];  // prop2 output (S rows valid)

// ---------------------------------------------------------------------------
// markS + zeroB fused
// ---------------------------------------------------------------------------
__global__ void markS_zeroB_kernel(const int* __restrict__ users,
                                   const int* __restrict__ items) {
    int t = blockIdx.x * blockDim.x + threadIdx.x;
    if (t >= 2 * NBATCH * 16) return;
    int elem = t >> 4, l = t & 15;
    int node = (elem < NBATCH) ? users[elem] : NU + items[elem - NBATCH];
    if (l == 0) gz.markS[node] = 1;
    reinterpret_cast<float4*>(g_bufB)[(size_t)node * 16 + l] =
        make_float4(0.f, 0.f, 0.f, 0.f);
}

// ---------------------------------------------------------------------------
// deg + scan1 fused, 4 edges/thread via int4 loads.
// deg[row]++ for all edges; edges with col in S -> markR[row]=1, append to
// list2 (unordered shared-atomic compaction: order is irrelevant downstream).
// ---------------------------------------------------------------------------
__global__ __launch_bounds__(256)
void deg_scan1_kernel(const int* __restrict__ ei) {
    __shared__ int sCnt, sBase;
    int tid = threadIdx.x;
    if (tid == 0) sCnt = 0;
    __syncthreads();

    int t = blockIdx.x * 256 + tid;
    int2 keep[4];
    int k = 0;
    if (t < NE / 4) {
        int4 r4 = reinterpret_cast<const int4*>(ei)[t];
        int4 c4 = reinterpret_cast<const int4*>(ei + NE)[t];
        atomicAdd(&gz.deg[r4.x], 1);
        atomicAdd(&gz.deg[r4.y], 1);
        atomicAdd(&gz.deg[r4.z], 1);
        atomicAdd(&gz.deg[r4.w], 1);
        if (gz.markS[c4.x]) { gz.markR[r4.x] = 1; keep[k++] = make_int2(r4.x, c4.x); }
        if (gz.markS[c4.y]) { gz.markR[r4.y] = 1; keep[k++] = make_int2(r4.y, c4.y); }
        if (gz.markS[c4.z]) { gz.markR[r4.z] = 1; keep[k++] = make_int2(r4.z, c4.z); }
        if (gz.markS[c4.w]) { gz.markR[r4.w] = 1; keep[k++] = make_int2(r4.w, c4.w); }
    }
    int off = 0;
    if (k) off = atomicAdd(&sCnt, k);
    __syncthreads();
    if (tid == 0) sBase = sCnt ? atomicAdd(&gz.cnt2, sCnt) : 0;
    __syncthreads();
    int base = sBase + off;
    for (int j = 0; j < k; j++) g_rc2[base + j] = keep[j];
}

// ---------------------------------------------------------------------------
// scan2 + zeroA fused, 4 edges/thread.
// phase A: edges with col in R -> append (row,col)+w to list1 (deg final,
//          both endpoints have deg>=1 so w>0).
// phase B: zero bufA rows in R (grid-stride, full-line writes).
// ---------------------------------------------------------------------------
__global__ __launch_bounds__(256)
void scan2_zeroA_kernel(const int* __restrict__ ei) {
    __shared__ int sCnt, sBase;
    int tid = threadIdx.x;
    if (tid == 0) sCnt = 0;
    __syncthreads();

    int t = blockIdx.x * 256 + tid;
    int2 keep[4];
    int k = 0;
    if (t < NE / 4) {
        int4 r4 = reinterpret_cast<const int4*>(ei)[t];
        int4 c4 = reinterpret_cast<const int4*>(ei + NE)[t];
        if (gz.markR[c4.x]) keep[k++] = make_int2(r4.x, c4.x);
        if (gz.markR[c4.y]) keep[k++] = make_int2(r4.y, c4.y);
        if (gz.markR[c4.z]) keep[k++] = make_int2(r4.z, c4.z);
        if (gz.markR[c4.w]) keep[k++] = make_int2(r4.w, c4.w);
    }
    int off = 0;
    if (k) off = atomicAdd(&sCnt, k);
    __syncthreads();
    if (tid == 0) sBase = sCnt ? atomicAdd(&gz.cnt1, sCnt) : 0;
    __syncthreads();
    int base = sBase + off;
    for (int j = 0; j < k; j++) {
        int2 rc = keep[j];
        g_rc1[base + j] = rc;
        g_w1[base + j]  = rsqrtf((float)gz.deg[rc.x]) * rsqrtf((float)gz.deg[rc.y]);
    }

    // phase B: zero bufA rows in R
    long long total = (long long)NN * 16;
    for (long long s = (long long)blockIdx.x * 256 + tid; s < total;
         s += (long long)gridDim.x * 256) {
        int r = (int)(s >> 4);
        if (gz.markR[r])
            reinterpret_cast<float4*>(g_bufA)[s] = make_float4(0.f, 0.f, 0.f, 0.f);
    }
}

// ---------------------------------------------------------------------------
// prop1 over list1: bufA[col] += w * emb[row]
// 16 threads/edge, one LDG.128 + one RED.128 each -> 4 wavefronts/edge
// (the hardware floor: 2 full lines in + 2 full lines out). Unroll x2 for MLP.
// ---------------------------------------------------------------------------
__global__ __launch_bounds__(256)
void prop1_kernel(const float* __restrict__ ue,
                  const float* __restrict__ ie) {
    int cnt = gz.cnt1;
    int t = blockIdx.x * 256 + threadIdx.x;
    int l = t & 15;
    int i0 = t >> 4;
    int stride = (gridDim.x * 256) >> 4;

    int i = i0;
    for (; i + stride < cnt; i += 2 * stride) {
        int  ia = i, ib = i + stride;
        int2 rca = g_rc1[ia];
        int2 rcb = g_rc1[ib];
        float wa = g_w1[ia];
        float wb = g_w1[ib];
        const float4* pa = reinterpret_cast<const float4*>(
            (rca.x < NU) ? (ue + (size_t)rca.x * DIM)
                         : (ie + (size_t)(rca.x - NU) * DIM));
        const float4* pb = reinterpret_cast<const float4*>(
            (rcb.x < NU) ? (ue + (size_t)rcb.x * DIM)
                         : (ie + (size_t)(rcb.x - NU) * DIM));
        float4 va = pa[l];
        float4 vb = pb[l];
        float* da = g_bufA + (size_t)rca.y * DIM + l * 4;
        float* db = g_bufA + (size_t)rcb.y * DIM + l * 4;
        asm volatile("red.global.add.v4.f32 [%0], {%1,%2,%3,%4};"
                     :: "l"(da), "f"(va.x * wa), "f"(va.y * wa),
                        "f"(va.z * wa), "f"(va.w * wa) : "memory");
        asm volatile("red.global.add.v4.f32 [%0], {%1,%2,%3,%4};"
                     :: "l"(db), "f"(vb.x * wb), "f"(vb.y * wb),
                        "f"(vb.z * wb), "f"(vb.w * wb) : "memory");
    }
    for (; i < cnt; i += stride) {
        int2 rc = g_rc1[i];
        float w = g_w1[i];
        const float4* p = reinterpret_cast<const float4*>(
            (rc.x < NU) ? (ue + (size_t)rc.x * DIM)
                        : (ie + (size_t)(rc.x - NU) * DIM));
        float4 v = p[l];
        float* dst = g_bufA + (size_t)rc.y * DIM + l * 4;
        asm volatile("red.global.add.v4.f32 [%0], {%1,%2,%3,%4};"
                     :: "l"(dst), "f"(v.x * w), "f"(v.y * w),
                        "f"(v.z * w), "f"(v.w * w) : "memory");
    }
}

// ---------------------------------------------------------------------------
// prop2 over list2: bufB[col] += w * relu(bufA[row] @ W1.T + b1)
// 16 threads/edge; row vector broadcast via width-16 shuffles; W1 in smem.
// ---------------------------------------------------------------------------
__global__ __launch_bounds__(256)
void prop2_kernel(const float* __restrict__ W1,
                  const float* __restrict__ b1) {
    __shared__ float sW[DIM * KP];
    __shared__ float sb[DIM];

    int tid = threadIdx.x;
    int cnt = gz.cnt2;

    for (int i = tid; i < DIM * 16; i += 256) {
        int r = i >> 4, k4 = i & 15;
        float4 v = reinterpret_cast<const float4*>(W1)[i];
        *reinterpret_cast<float4*>(&sW[r * KP + k4 * 4]) = v;
    }
    if (tid < DIM) sb[tid] = b1[tid];
    __syncthreads();

    int gi = tid >> 4;
    int l  = tid & 15;
    int c0 = l * 4;

    for (int base = blockIdx.x * 16; base < cnt; base += gridDim.x * 16) {
        int idx = base + gi;
        bool act = idx < cnt;

        int2 rc = g_rc2[act ? idx : 0];
        int dc = gz.deg[rc.y];
        float w = (dc > 0) ? rsqrtf((float)gz.deg[rc.x]) * rsqrtf((float)dc) : 0.0f;
        act = act && (w != 0.0f);

        float4 a = make_float4(0.f, 0.f, 0.f, 0.f);
        if (act) a = reinterpret_cast<const float4*>(g_bufA)[(size_t)rc.x * 16 + l];

        float acc0 = sb[c0], acc1 = sb[c0 + 1], acc2 = sb[c0 + 2], acc3 = sb[c0 + 3];

#pragma unroll
        for (int k4 = 0; k4 < 16; k4++) {
            float x0 = __shfl_sync(0xffffffffu, a.x, k4, 16);
            float x1 = __shfl_sync(0xffffffffu, a.y, k4, 16);
            float x2 = __shfl_sync(0xffffffffu, a.z, k4, 16);
            float x3 = __shfl_sync(0xffffffffu, a.w, k4, 16);
            float4 w0 = *reinterpret_cast<const float4*>(&sW[(c0 + 0) * KP + k4 * 4]);
            float4 w1 = *reinterpret_cast<const float4*>(&sW[(c0 + 1) * KP + k4 * 4]);
            float4 w2 = *reinterpret_cast<const float4*>(&sW[(c0 + 2) * KP + k4 * 4]);
            float4 w3 = *reinterpret_cast<const float4*>(&sW[(c0 + 3) * KP + k4 * 4]);
            acc0 += x0 * w0.x + x1 * w0.y + x2 * w0.z + x3 * w0.w;
            acc1 += x0 * w1.x + x1 * w1.y + x2 * w1.z + x3 * w1.w;
            acc2 += x0 * w2.x + x1 * w2.y + x2 * w2.z + x3 * w2.w;
            acc3 += x0 * w3.x + x1 * w3.y + x2 * w3.z + x3 * w3.w;
        }

        if (act) {
            float m0 = fmaxf(acc0, 0.f) * w;
            float m1 = fmaxf(acc1, 0.f) * w;
            float m2 = fmaxf(acc2, 0.f) * w;
            float m3 = fmaxf(acc3, 0.f) * w;
            float* dst = g_bufB + (size_t)rc.y * DIM + c0;
            asm volatile("red.global.add.v4.f32 [%0], {%1,%2,%3,%4};"
                         :: "l"(dst), "f"(m0), "f"(m1), "f"(m2), "f"(m3)
                         : "memory");
        }
    }
}

// ---------------------------------------------------------------------------
// score: 512 blocks x 8 warps; ONE warp per batch element.
// ---------------------------------------------------------------------------
__global__ __launch_bounds__(256)
void score_kernel(const int* __restrict__ users,
                  const int* __restrict__ items,
                  const float* __restrict__ W2,
                  const float* __restrict__ b2,
                  float* __restrict__ out) {
    __shared__ float sW[DIM * KP];
    __shared__ float sb[DIM];
    __shared__ float4 sUV[8][2][16];

    int tid = threadIdx.x;
    for (int i = tid; i < DIM * 16; i += 256) {
        int r = i >> 4, k4 = i & 15;
        float4 v = reinterpret_cast<const float4*>(W2)[i];
        *reinterpret_cast<float4*>(&sW[r * KP + k4 * 4]) = v;
    }
    if (tid < DIM) sb[tid] = b2[tid];
    __syncthreads();

    int wid = tid >> 5, lane = tid & 31;
    int bi = blockIdx.x * 8 + wid;

    int u  = users[bi];
    int it = items[bi];
    if (lane < 16)
        sUV[wid][0][lane] = reinterpret_cast<const float4*>(g_bufB)[(size_t)u * 16 + lane];
    else
        sUV[wid][1][lane - 16] =
            reinterpret_cast<const float4*>(g_bufB)[(size_t)(NU + it) * 16 + (lane - 16)];
    __syncwarp();

    float uo = sb[lane], vo = sb[lane];
    float uo1 = sb[lane + 32], vo1 = sb[lane + 32];
#pragma unroll
    for (int k4 = 0; k4 < 16; k4++) {
        float4 su4 = sUV[wid][0][k4];
        float4 sv4 = sUV[wid][1][k4];
        float4 wa  = *reinterpret_cast<const float4*>(&sW[lane * KP + k4 * 4]);
        float4 wb  = *reinterpret_cast<const float4*>(&sW[(lane + 32) * KP + k4 * 4]);
        uo  += su4.x * wa.x + su4.y * wa.y + su4.z * wa.z + su4.w * wa.w;
        vo  += sv4.x * wa.x + sv4.y * wa.y + sv4.z * wa.z + sv4.w * wa.w;
        uo1 += su4.x * wb.x + su4.y * wb.y + su4.z * wb.z + su4.w * wb.w;
        vo1 += sv4.x * wb.x + sv4.y * wb.y + sv4.z * wb.z + sv4.w * wb.w;
    }
    float s = uo * vo + uo1 * vo1;
#pragma unroll
    for (int o = 16; o > 0; o >>= 1)
        s += __shfl_down_sync(0xffffffffu, s, o);
    if (lane == 0) out[bi] = s;
}

// ---------------------------------------------------------------------------
extern "C" void kernel_launch(void* const* d_in, const int* in_sizes, int n_in,
                              void* d_out, int out_size) {
    const int*   users = (const int*)d_in[0];
    const int*   items = (const int*)d_in[1];
    const int*   ei    = (const int*)d_in[2];
    const float* ue    = (const float*)d_in[3];
    const float* ie    = (const float*)d_in[4];
    const float* W1    = (const float*)d_in[5];
    const float* b1    = (const float*)d_in[6];
    const float* W2    = (const float*)d_in[7];
    const float* b2    = (const float*)d_in[8];
    float* out = (float*)d_out;

    void* pZ;
    cudaGetSymbolAddress(&pZ, gz);
    cudaMemsetAsync(pZ, 0, sizeof(ZeroBlock), 0);

    markS_zeroB_kernel<<<(2 * NBATCH * 16 + 255) / 256, 256>>>(users, items);
    deg_scan1_kernel<<<(NE / 4 + 255) / 256, 256>>>(ei);
    scan2_zeroA_kernel<<<(NE / 4 + 255) / 256, 256>>>(ei);
    prop1_kernel<<<1024, 256>>>(ue, ie);
    prop2_kernel<<<1024, 256>>>(W1, b1);
    score_kernel<<<NBATCH / 8, 256>>>(users, items, W2, b2, out);
}